// round 2
// baseline (speedup 1.0000x reference)
#include <cuda_runtime.h>
#include <math.h>

#define N      4096
#define DIMS   8
#define REGL   1e-3f
#define ITER   64            // MUST stay even (barrier sense invariant across graph replays)
#define GRID   128
#define BLOCK  256
#define RPB    (N / GRID)    // 32 rows/elements owned per block

// ---------------- device scratch (no allocations allowed) ----------------
__device__ float4 d_ftr[DIMS * N];        // train features per dim: (x, cos(x/2), sin(x/2), 0)
__device__ float  d_ntr[N];               // train ||x||^2
__device__ float4 d_fte[DIMS * N];        // test features
__device__ float  d_nte[N];
__device__ float  d_A [(size_t)N * N];    // K_train + reg*I   (64 MB)
__device__ float  d_KT[(size_t)N * N];    // K_test            (64 MB)
__device__ float  d_x[N], d_r[N], d_p[N], d_q[N];
__device__ float  d_ppq[GRID], d_prr[GRID];

// ---------------- software grid barrier (sense-reversing) ----------------
__device__ unsigned d_barcnt   = 0;
__device__ unsigned d_barsense = 0;

__device__ __forceinline__ void gbar(unsigned* lsense) {
    __syncthreads();
    if (threadIdx.x == 0) {
        unsigned s = *lsense ^ 1u;
        *lsense = s;
        __threadfence();
        unsigned a = atomicAdd(&d_barcnt, 1u);
        if (a == GRID - 1) {
            d_barcnt = 0;
            __threadfence();
            atomicExch(&d_barsense, s);
        } else {
            while (atomicAdd(&d_barsense, 0u) != s) { }
        }
        __threadfence();
    }
    __syncthreads();
}

// ---------------- the whole pipeline in one persistent kernel ----------------
__global__ __launch_bounds__(BLOCK)
void mega_kernel(const float* __restrict__ Xtr, const float* __restrict__ ytr,
                 const float* __restrict__ Xte, float* __restrict__ out) {
    __shared__ float  s_v[N];            // 16 KB: p (or x) for matvec
    __shared__ float4 s_tf[DIMS][32];    // build: row features
    __shared__ float  s_tn[32];
    __shared__ float  s_red[8];
    __shared__ float  s_scal[4];

    unsigned lsense = 0;
    const int tid = threadIdx.x, blk = blockIdx.x;
    const int warp = tid >> 5, lane = tid & 31;

    // ===== Phase A: per-point features + CG vector init =====
    for (int i = blk * BLOCK + tid; i < 2 * N; i += GRID * BLOCK) {
        const int   j  = (i < N) ? i : i - N;
        const float* X = (i < N) ? Xtr : Xte;
        float4* fd = (i < N) ? d_ftr : d_fte;
        float*  fn = (i < N) ? d_ntr : d_nte;
        float nrm = 0.f;
#pragma unroll
        for (int d = 0; d < DIMS; d++) {
            float v = X[j * DIMS + d];
            nrm = fmaf(v, v, nrm);
            float s, c;
            __sincosf(0.5f * v, &s, &c);
            fd[d * N + j] = make_float4(v, c, s, 0.f);
        }
        fn[j] = nrm;
    }
    if (tid < RPB) {
        int e = blk * RPB + tid;
        float v = ytr[e];
        d_x[e] = 0.f; d_r[e] = v; d_p[e] = v;
    }
    gbar(&lsense);                                                   // bar #1

    // ===== Phase B: build A (m=0) and K_test (m=1); tiles of 32 rows x 256 cols =====
    // tiles per matrix = (N/32)*(N/256) = 128*16 = 2048; total 4096 over GRID blocks
    for (int t = blk; t < 2 * 2048; t += GRID) {
        const int m    = t >> 11;
        const int tt   = t & 2047;
        const int rowT = tt >> 4, colT = tt & 15;
        const float4* fR = m ? d_fte : d_ftr;
        const float*  nR = m ? d_nte : d_ntr;
        float* dst = m ? d_KT : d_A;

        for (int k = tid; k < 32 * DIMS; k += BLOCK) {
            int d = k >> 5, rr = k & 31;
            s_tf[d][rr] = fR[d * N + rowT * 32 + rr];
        }
        if (tid < 32) s_tn[tid] = nR[rowT * 32 + tid];
        __syncthreads();

        const int col = colT * 256 + tid;
        float4 cf[DIMS];
#pragma unroll
        for (int d = 0; d < DIMS; d++) cf[d] = d_ftr[d * N + col];
        const float cn = d_ntr[col];

#pragma unroll 4
        for (int rr = 0; rr < 32; rr++) {
            float dot = 0.f, prod = 1.f;
#pragma unroll
            for (int d = 0; d < DIMS; d++) {
                float4 rf = s_tf[d][rr];
                dot  = fmaf(rf.x, cf[d].x, dot);
                prod *= fmaf(rf.z, cf[d].z, rf.y * cf[d].y);
            }
            float sq  = s_tn[rr] + cn - 2.f * dot;
            float val = __expf(-sq) * fabsf(prod);
            int row = rowT * 32 + rr;
            if (m == 0 && row == col) val += REGL;
            dst[(size_t)row * N + col] = val;
        }
        __syncthreads();
    }

    // rs0 = y.y  (every block computes the identical value deterministically)
    float part = 0.f;
    for (int i = tid; i < N; i += BLOCK) { float v = ytr[i]; part = fmaf(v, v, part); }
#pragma unroll
    for (int o = 16; o; o >>= 1) part += __shfl_xor_sync(0xffffffffu, part, o);
    if (lane == 0) s_red[warp] = part;
    __syncthreads();
    if (tid == 0) { float s = 0.f; for (int k = 0; k < 8; k++) s += s_red[k]; s_scal[0] = s; }
    __syncthreads();
    float rs = s_scal[0];
    gbar(&lsense);                                                   // bar #2

    // ===== Phase C: CG loop =====
    for (int it = 0; it < ITER; it++) {
        // stage p in shared
        for (int i = tid; i < N; i += BLOCK) s_v[i] = d_p[i];
        __syncthreads();

        // q = A p  (row-per-warp, 4 rows/warp) + partial p.q per block
        float pq_acc = 0.f;
#pragma unroll
        for (int j = 0; j < 4; j++) {
            const int row = blk * RPB + warp * 4 + j;
            const float4* Ar = (const float4*)(d_A + (size_t)row * N);
            const float4* vv = (const float4*)s_v;
            float sum = 0.f;
#pragma unroll 8
            for (int c = lane; c < N / 4; c += 32) {
                float4 a = Ar[c], b = vv[c];
                sum = fmaf(a.x, b.x, fmaf(a.y, b.y, fmaf(a.z, b.z, fmaf(a.w, b.w, sum))));
            }
#pragma unroll
            for (int o = 16; o; o >>= 1) sum += __shfl_xor_sync(0xffffffffu, sum, o);
            if (lane == 0) {
                d_q[row] = sum;
                pq_acc = fmaf(sum, s_v[row], pq_acc);
            }
        }
        if (lane == 0) s_red[warp] = pq_acc;
        __syncthreads();
        if (tid == 0) { float s = 0.f; for (int k = 0; k < 8; k++) s += s_red[k]; d_ppq[blk] = s; }
        gbar(&lsense);                                               // bar (3k+3)

        if (tid == 0) { float s = 0.f; for (int k = 0; k < GRID; k++) s += d_ppq[k]; s_scal[1] = s; }
        __syncthreads();
        const float pAp   = s_scal[1];
        const float alpha = (pAp > 0.f && rs > 0.f) ? rs / pAp : 0.f;

        float rrp = 0.f;
        if (tid < RPB) {
            int e = blk * RPB + tid;
            float pv = s_v[e], qv = d_q[e];
            d_x[e] = fmaf(alpha, pv, d_x[e]);
            float rv = fmaf(-alpha, qv, d_r[e]);
            d_r[e] = rv;
            rrp = rv * rv;
        }
        if (warp == 0) {
#pragma unroll
            for (int o = 16; o; o >>= 1) rrp += __shfl_xor_sync(0xffffffffu, rrp, o);
            if (lane == 0) d_prr[blk] = rrp;
        }
        gbar(&lsense);                                               // bar (3k+4)

        if (tid == 0) { float s = 0.f; for (int k = 0; k < GRID; k++) s += d_prr[k]; s_scal[2] = s; }
        __syncthreads();
        const float rsnew = s_scal[2];
        const float beta  = (rs > 0.f) ? rsnew / rs : 0.f;
        rs = rsnew;
        if (tid < RPB) {
            int e = blk * RPB + tid;
            d_p[e] = fmaf(beta, s_v[e], d_r[e]);
        }
        gbar(&lsense);                                               // bar (3k+5)
    }

    // ===== Phase D: y_pred = K_test @ alpha  =====
    for (int i = tid; i < N; i += BLOCK) s_v[i] = d_x[i];
    __syncthreads();
#pragma unroll
    for (int j = 0; j < 4; j++) {
        const int row = blk * RPB + warp * 4 + j;
        const float4* Kr = (const float4*)(d_KT + (size_t)row * N);
        const float4* vv = (const float4*)s_v;
        float sum = 0.f;
#pragma unroll 8
        for (int c = lane; c < N / 4; c += 32) {
            float4 a = Kr[c], b = vv[c];
            sum = fmaf(a.x, b.x, fmaf(a.y, b.y, fmaf(a.z, b.z, fmaf(a.w, b.w, sum))));
        }
#pragma unroll
        for (int o = 16; o; o >>= 1) sum += __shfl_xor_sync(0xffffffffu, sum, o);
        if (lane == 0) out[row] = sum;
    }
    // total gbar calls: 2 + 3*ITER  (even) -> barrier sense returns to 0 for next replay
}

// ---------------- launch ----------------
extern "C" void kernel_launch(void* const* d_in, const int* in_sizes, int n_in,
                              void* d_out, int out_size) {
    const float* Xtr = (const float*)d_in[0];
    const float* ytr = (const float*)d_in[1];
    const float* Xte = (const float*)d_in[2];
    mega_kernel<<<GRID, BLOCK>>>(Xtr, ytr, Xte, (float*)d_out);
}

// round 4
// speedup vs baseline: 2.0151x; 2.0151x over previous
#include <cuda_runtime.h>
#include <math.h>

#define N      4096
#define DIMS   8
#define REGL   1e-3f
#define ITER   40            // MUST stay even (barrier sense invariant across graph replays)
#define GRID   128
#define BLOCK  512
#define RPB    (N / GRID)    // 32 rows/elements owned per block
#define NWARP  (BLOCK / 32)  // 16

// ---------------- device scratch (no allocations allowed) ----------------
__device__ float4 d_ftr[DIMS * N];        // train features per dim: (x, cos(x/2), sin(x/2), 0)
__device__ float  d_ntr[N];               // train ||x||^2
__device__ float4 d_fte[DIMS * N];        // test features
__device__ float  d_nte[N];
__device__ float  d_A [(size_t)N * N];    // K_train + reg*I   (64 MB)
__device__ float  d_KT[(size_t)N * N];    // K_test            (64 MB)
__device__ float  d_x[N], d_r[N], d_p[N], d_q[N];
__device__ float  d_ppq[GRID], d_prr[GRID];

// ---------------- software grid barrier (sense-reversing, R2-proven) ----------------
__device__ unsigned d_barcnt   = 0;
__device__ unsigned d_barsense = 0;

__device__ __forceinline__ void gbar(unsigned* lsense) {
    __syncthreads();
    if (threadIdx.x == 0) {
        unsigned s = *lsense ^ 1u;
        *lsense = s;
        __threadfence();
        unsigned a = atomicAdd(&d_barcnt, 1u);
        if (a == GRID - 1) {
            d_barcnt = 0;
            __threadfence();
            atomicExch(&d_barsense, s);
        } else {
            while (atomicAdd(&d_barsense, 0u) != s) { }
        }
        __threadfence();
    }
    __syncthreads();
}

// ---------------- the whole pipeline in one persistent kernel ----------------
__global__ __launch_bounds__(BLOCK)
void mega_kernel(const float* __restrict__ Xtr, const float* __restrict__ ytr,
                 const float* __restrict__ Xte, float* __restrict__ out) {
    __shared__ float  s_v[N];            // 16 KB: p (or x) for matvec
    __shared__ float4 s_tf[DIMS][32];    // build: row features
    __shared__ float  s_tn[32];
    __shared__ float  s_red[NWARP];
    __shared__ float  s_scal[4];

    unsigned lsense = 0;
    const int tid = threadIdx.x, blk = blockIdx.x;
    const int warp = tid >> 5, lane = tid & 31;

    // ===== Phase A: per-point features + CG vector init =====
    for (int i = blk * BLOCK + tid; i < 2 * N; i += GRID * BLOCK) {
        const int   j  = (i < N) ? i : i - N;
        const float* X = (i < N) ? Xtr : Xte;
        float4* fd = (i < N) ? d_ftr : d_fte;
        float*  fn = (i < N) ? d_ntr : d_nte;
        float nrm = 0.f;
#pragma unroll
        for (int d = 0; d < DIMS; d++) {
            float v = X[j * DIMS + d];
            nrm = fmaf(v, v, nrm);
            float s, c;
            __sincosf(0.5f * v, &s, &c);
            fd[d * N + j] = make_float4(v, c, s, 0.f);
        }
        fn[j] = nrm;
    }
    if (tid < RPB) {
        int e = blk * RPB + tid;
        float v = ytr[e];
        d_x[e] = 0.f; d_r[e] = v; d_p[e] = v;
    }
    gbar(&lsense);                                                   // bar #1

    // ===== Phase B: build A (m=0) and K_test (m=1); tiles of 32 rows x 512 cols =====
    // tiles per matrix = (N/32)*(N/512) = 128*8 = 1024; total 2048 over GRID blocks
    for (int t = blk; t < 2048; t += GRID) {
        const int m    = t >> 10;
        const int tt   = t & 1023;
        const int rowT = tt >> 3, colT = tt & 7;
        const float4* fR = m ? d_fte : d_ftr;
        const float*  nR = m ? d_nte : d_ntr;
        float* dst = m ? d_KT : d_A;

        for (int k = tid; k < 32 * DIMS; k += BLOCK) {
            int d = k >> 5, rr = k & 31;
            s_tf[d][rr] = fR[d * N + rowT * 32 + rr];
        }
        if (tid < 32) s_tn[tid] = nR[rowT * 32 + tid];
        __syncthreads();

        const int col = colT * 512 + tid;
        float4 cf[DIMS];
#pragma unroll
        for (int d = 0; d < DIMS; d++) cf[d] = d_ftr[d * N + col];
        const float cn = d_ntr[col];

#pragma unroll 4
        for (int rr = 0; rr < 32; rr++) {
            float dot = 0.f, prod = 1.f;
#pragma unroll
            for (int d = 0; d < DIMS; d++) {
                float4 rf = s_tf[d][rr];
                dot  = fmaf(rf.x, cf[d].x, dot);
                prod *= fmaf(rf.z, cf[d].z, rf.y * cf[d].y);
            }
            float sq  = s_tn[rr] + cn - 2.f * dot;
            float val = __expf(-sq) * fabsf(prod);
            int row = rowT * 32 + rr;
            if (m == 0 && row == col) val += REGL;
            dst[(size_t)row * N + col] = val;
        }
        __syncthreads();
    }

    // rs0 = y.y  (every block computes the identical value deterministically)
    float part = 0.f;
    for (int i = tid; i < N; i += BLOCK) { float v = ytr[i]; part = fmaf(v, v, part); }
#pragma unroll
    for (int o = 16; o; o >>= 1) part += __shfl_xor_sync(0xffffffffu, part, o);
    if (lane == 0) s_red[warp] = part;
    __syncthreads();
    if (tid == 0) {
        float s = 0.f;
        for (int k = 0; k < NWARP; k++) s += s_red[k];
        s_scal[0] = s;
    }
    __syncthreads();
    float rs = s_scal[0];
    gbar(&lsense);                                                   // bar #2

    // ===== Phase C: CG loop =====
    for (int it = 0; it < ITER; it++) {
        // stage p in shared
        for (int i = tid; i < N / 4; i += BLOCK) ((float4*)s_v)[i] = ((const float4*)d_p)[i];
        __syncthreads();

        // q = A p  (2 rows per warp) + partial p.q per block
        float pq_acc = 0.f;
#pragma unroll
        for (int j = 0; j < 2; j++) {
            const int row = blk * RPB + warp * 2 + j;
            const float4* Ar = (const float4*)(d_A + (size_t)row * N);
            const float4* vv = (const float4*)s_v;
            float sum = 0.f;
#pragma unroll 8
            for (int c = lane; c < N / 4; c += 32) {
                float4 a = Ar[c], b = vv[c];
                sum = fmaf(a.x, b.x, fmaf(a.y, b.y, fmaf(a.z, b.z, fmaf(a.w, b.w, sum))));
            }
#pragma unroll
            for (int o = 16; o; o >>= 1) sum += __shfl_xor_sync(0xffffffffu, sum, o);
            if (lane == 0) {
                d_q[row] = sum;
                pq_acc = fmaf(sum, s_v[row], pq_acc);
            }
        }
        if (lane == 0) s_red[warp] = pq_acc;
        __syncthreads();
        if (tid == 0) {
            float s = 0.f;
            for (int k = 0; k < NWARP; k++) s += s_red[k];
            d_ppq[blk] = s;
        }
        gbar(&lsense);                                               // bar (3k+3)

        if (tid == 0) {
            float s = 0.f;
            for (int k = 0; k < GRID; k++) s += d_ppq[k];
            s_scal[1] = s;
        }
        __syncthreads();
        const float pAp   = s_scal[1];
        const float alpha = (pAp > 0.f && rs > 0.f) ? rs / pAp : 0.f;

        float rrp = 0.f;
        if (tid < RPB) {
            int e = blk * RPB + tid;
            float pv = s_v[e], qv = d_q[e];
            d_x[e] = fmaf(alpha, pv, d_x[e]);
            float rv = fmaf(-alpha, qv, d_r[e]);
            d_r[e] = rv;
            rrp = rv * rv;
        }
        if (warp == 0) {
#pragma unroll
            for (int o = 16; o; o >>= 1) rrp += __shfl_xor_sync(0xffffffffu, rrp, o);
            if (lane == 0) d_prr[blk] = rrp;
        }
        gbar(&lsense);                                               // bar (3k+4)

        if (tid == 0) {
            float s = 0.f;
            for (int k = 0; k < GRID; k++) s += d_prr[k];
            s_scal[2] = s;
        }
        __syncthreads();
        const float rsnew = s_scal[2];
        const float beta  = (rs > 0.f) ? rsnew / rs : 0.f;
        rs = rsnew;
        if (tid < RPB) {
            int e = blk * RPB + tid;
            d_p[e] = fmaf(beta, s_v[e], d_r[e]);
        }
        gbar(&lsense);                                               // bar (3k+5)
    }

    // ===== Phase D: y_pred = K_test @ alpha  =====
    for (int i = tid; i < N / 4; i += BLOCK) ((float4*)s_v)[i] = ((const float4*)d_x)[i];
    __syncthreads();
#pragma unroll
    for (int j = 0; j < 2; j++) {
        const int row = blk * RPB + warp * 2 + j;
        const float4* Kr = (const float4*)(d_KT + (size_t)row * N);
        const float4* vv = (const float4*)s_v;
        float sum = 0.f;
#pragma unroll 8
        for (int c = lane; c < N / 4; c += 32) {
            float4 a = Kr[c], b = vv[c];
            sum = fmaf(a.x, b.x, fmaf(a.y, b.y, fmaf(a.z, b.z, fmaf(a.w, b.w, sum))));
        }
#pragma unroll
        for (int o = 16; o; o >>= 1) sum += __shfl_xor_sync(0xffffffffu, sum, o);
        if (lane == 0) out[row] = sum;
    }
    // total gbar calls: 2 + 3*ITER  (even) -> barrier sense returns to 0 for next replay
}

// ---------------- launch ----------------
extern "C" void kernel_launch(void* const* d_in, const int* in_sizes, int n_in,
                              void* d_out, int out_size) {
    const float* Xtr = (const float*)d_in[0];
    const float* ytr = (const float*)d_in[1];
    const float* Xte = (const float*)d_in[2];
    mega_kernel<<<GRID, BLOCK>>>(Xtr, ytr, Xte, (float*)d_out);
}

// round 5
// speedup vs baseline: 2.6113x; 1.2959x over previous
#include <cuda_runtime.h>
#include <math.h>

#define N      4096
#define DIMS   8
#define REGL   1e-3f
#define ITER   40
#define GRID   128
#define BLOCK  512
#define RPB    (N / GRID)        // 32 rows owned per block
#define NWARP  (BLOCK / 32)      // 16
#define VPT    (N / 4 / BLOCK)   // 2 float4 per thread in vector ops

// ---------------- device scratch (no allocations allowed) ----------------
__device__ float4 d_ftr[DIMS * N];        // train features: (x, cos(x/2), sin(x/2), 0)
__device__ float  d_ntr[N];
__device__ float4 d_fte[DIMS * N];
__device__ float  d_nte[N];
__device__ float  d_A [(size_t)N * N];    // K_train + reg*I   (64 MB)
__device__ float  d_KT[(size_t)N * N];    // K_test            (64 MB)
__device__ float  d_x[N], d_q[N];
__device__ float  d_ppq[GRID];

// ---------------- flag-tree grid barrier (sense-reversing) ----------------
__device__ volatile unsigned d_flag[GRID];   // zero-init; returns to 0 (even # bars)
__device__ volatile unsigned d_rel;

__device__ __forceinline__ void gbar(unsigned* lsense) {
    const unsigned s = *lsense ^ 1u;
    *lsense = s;
    __syncthreads();
    if (blockIdx.x == 0) {
        __threadfence();
        const int t = threadIdx.x;
        if (t >= 1 && t < GRID) { while (d_flag[t] != s) { } }
        __syncthreads();
        if (t == 0) { __threadfence(); d_rel = s; }
        __threadfence();
    } else {
        if (threadIdx.x == 0) {
            __threadfence();
            d_flag[blockIdx.x] = s;
            while (d_rel != s) { }
            __threadfence();
        }
    }
    __syncthreads();
}

// ---------------- the whole pipeline in one persistent kernel ----------------
__global__ __launch_bounds__(BLOCK)
void mega_kernel(const float* __restrict__ Xtr, const float* __restrict__ ytr,
                 const float* __restrict__ Xte, float* __restrict__ out) {
    __shared__ __align__(16) float s_p[N];   // 16 KB: full p (identical in all blocks)
    __shared__ __align__(16) float s_r[N];   // 16 KB: full r (identical in all blocks)
    __shared__ float4 s_tf[DIMS][32];
    __shared__ float  s_tn[32];
    __shared__ float  s_red[NWARP];
    __shared__ float  s_bc[2];

    unsigned lsense = 0;
    const int tid = threadIdx.x, blk = blockIdx.x;
    const int warp = tid >> 5, lane = tid & 31;

    // ===== Phase A: per-point features =====
    for (int i = blk * BLOCK + tid; i < 2 * N; i += GRID * BLOCK) {
        const int   j  = (i < N) ? i : i - N;
        const float* X = (i < N) ? Xtr : Xte;
        float4* fd = (i < N) ? d_ftr : d_fte;
        float*  fn = (i < N) ? d_ntr : d_nte;
        float nrm = 0.f;
#pragma unroll
        for (int d = 0; d < DIMS; d++) {
            float v = X[j * DIMS + d];
            nrm = fmaf(v, v, nrm);
            float s, c;
            __sincosf(0.5f * v, &s, &c);
            fd[d * N + j] = make_float4(v, c, s, 0.f);
        }
        fn[j] = nrm;
    }
    if (tid < RPB) d_x[blk * RPB + tid] = 0.f;
    gbar(&lsense);                                                   // bar #1

    // ===== Phase B: build A (m=0) and K_test (m=1); 32-row x 512-col tiles =====
    for (int t = blk; t < 2048; t += GRID) {
        const int m    = t >> 10;
        const int tt   = t & 1023;
        const int rowT = tt >> 3, colT = tt & 7;
        const float4* fR = m ? d_fte : d_ftr;
        const float*  nR = m ? d_nte : d_ntr;
        float* dst = m ? d_KT : d_A;

        for (int k = tid; k < 32 * DIMS; k += BLOCK) {
            int d = k >> 5, rr = k & 31;
            s_tf[d][rr] = fR[d * N + rowT * 32 + rr];
        }
        if (tid < 32) s_tn[tid] = nR[rowT * 32 + tid];
        __syncthreads();

        const int col = colT * 512 + tid;
        float4 cf[DIMS];
#pragma unroll
        for (int d = 0; d < DIMS; d++) cf[d] = d_ftr[d * N + col];
        const float cn = d_ntr[col];

#pragma unroll 4
        for (int rr = 0; rr < 32; rr++) {
            float dot = 0.f, prod = 1.f;
#pragma unroll
            for (int d = 0; d < DIMS; d++) {
                float4 rf = s_tf[d][rr];
                dot  = fmaf(rf.x, cf[d].x, dot);
                prod *= fmaf(rf.z, cf[d].z, rf.y * cf[d].y);
            }
            float sq  = s_tn[rr] + cn - 2.f * dot;
            float val = __expf(-sq) * fabsf(prod);
            int row = rowT * 32 + rr;
            if (m == 0 && row == col) val += REGL;
            dst[(size_t)row * N + col] = val;
        }
        __syncthreads();
    }

    // ===== CG init: r = p = y in smem (every block), rs = y.y (block-local, identical) =====
    float part = 0.f;
    for (int i = tid; i < N; i += BLOCK) {
        float v = ytr[i];
        s_r[i] = v; s_p[i] = v;
        part = fmaf(v, v, part);
    }
#pragma unroll
    for (int o = 16; o; o >>= 1) part += __shfl_xor_sync(0xffffffffu, part, o);
    if (lane == 0) s_red[warp] = part;
    __syncthreads();
    if (tid == 0) {
        float s = 0.f;
        for (int k = 0; k < NWARP; k++) s += s_red[k];
        s_bc[0] = s;
    }
    __syncthreads();
    float rs = s_bc[0];
    gbar(&lsense);                                                   // bar #2 (covers build)

    // ===== CG loop: 2 barriers per iteration =====
    for (int it = 0; it < ITER; it++) {
        // --- q[own rows] = A[own rows] * p ; per-block partial p.q ---
        float pq_acc = 0.f;
#pragma unroll
        for (int j = 0; j < 2; j++) {
            const int row = blk * RPB + warp * 2 + j;
            const float4* Ar = (const float4*)(d_A + (size_t)row * N);
            const float4* vv = (const float4*)s_p;
            float sum = 0.f;
#pragma unroll 8
            for (int c = lane; c < N / 4; c += 32) {
                float4 a = Ar[c], b = vv[c];
                sum = fmaf(a.x, b.x, fmaf(a.y, b.y, fmaf(a.z, b.z, fmaf(a.w, b.w, sum))));
            }
#pragma unroll
            for (int o = 16; o; o >>= 1) sum += __shfl_xor_sync(0xffffffffu, sum, o);
            if (lane == 0) {
                d_q[row] = sum;
                pq_acc = fmaf(sum, s_p[row], pq_acc);
            }
        }
        if (lane == 0) s_red[warp] = pq_acc;
        __syncthreads();
        if (tid == 0) {
            float s = 0.f;
            for (int k = 0; k < NWARP; k++) s += s_red[k];
            d_ppq[blk] = s;
        }
        gbar(&lsense);                                               // bar (2k+3): q + partials ready

        // --- pAp: every block reduces the 128 partials identically ---
        if (tid < GRID) {
            float v = __ldcg((const float*)&d_ppq[tid]);
#pragma unroll
            for (int o = 16; o; o >>= 1) v += __shfl_xor_sync(0xffffffffu, v, o);
            if (lane == 0) s_red[warp] = v;
        }
        __syncthreads();
        if (tid == 0) s_bc[1] = ((s_red[0] + s_red[1]) + (s_red[2] + s_red[3]));
        __syncthreads();
        const float pAp   = s_bc[1];
        const float alpha = (pAp > 0.f && rs > 0.f) ? rs / pAp : 0.f;

        // --- full r update (redundant per block, identical) + block-local rr ---
        float rrp = 0.f;
#pragma unroll
        for (int k = 0; k < VPT; k++) {
            const int i = tid + k * BLOCK;
            float4 qv = __ldcg(((const float4*)d_q) + i);
            float4 rv = ((float4*)s_r)[i];
            rv.x = fmaf(-alpha, qv.x, rv.x);
            rv.y = fmaf(-alpha, qv.y, rv.y);
            rv.z = fmaf(-alpha, qv.z, rv.z);
            rv.w = fmaf(-alpha, qv.w, rv.w);
            ((float4*)s_r)[i] = rv;
            rrp = fmaf(rv.x, rv.x, fmaf(rv.y, rv.y, fmaf(rv.z, rv.z, fmaf(rv.w, rv.w, rrp))));
        }
        // x update: own rows only
        if (tid < RPB) {
            int e = blk * RPB + tid;
            d_x[e] = fmaf(alpha, s_p[e], d_x[e]);
        }
#pragma unroll
        for (int o = 16; o; o >>= 1) rrp += __shfl_xor_sync(0xffffffffu, rrp, o);
        if (lane == 0) s_red[warp] = rrp;
        __syncthreads();
        if (tid == 0) {
            float s = 0.f;
            for (int k = 0; k < NWARP; k++) s += s_red[k];
            s_bc[0] = s;
        }
        __syncthreads();
        const float rsnew = s_bc[0];
        const float beta  = (rs > 0.f) ? rsnew / rs : 0.f;
        rs = rsnew;

        // --- full p update (redundant per block, identical) ---
#pragma unroll
        for (int k = 0; k < VPT; k++) {
            const int i = tid + k * BLOCK;
            float4 pv = ((float4*)s_p)[i];
            float4 rv = ((float4*)s_r)[i];
            pv.x = fmaf(beta, pv.x, rv.x);
            pv.y = fmaf(beta, pv.y, rv.y);
            pv.z = fmaf(beta, pv.z, rv.z);
            pv.w = fmaf(beta, pv.w, rv.w);
            ((float4*)s_p)[i] = pv;
        }
        gbar(&lsense);                                               // bar (2k+4): q/ppq consumable again
    }

    // ===== Predict: y_pred = K_test @ x =====
#pragma unroll
    for (int k = 0; k < VPT; k++) {
        const int i = tid + k * BLOCK;
        ((float4*)s_p)[i] = __ldcg(((const float4*)d_x) + i);
    }
    __syncthreads();
#pragma unroll
    for (int j = 0; j < 2; j++) {
        const int row = blk * RPB + warp * 2 + j;
        const float4* Kr = (const float4*)(d_KT + (size_t)row * N);
        const float4* vv = (const float4*)s_p;
        float sum = 0.f;
#pragma unroll 8
        for (int c = lane; c < N / 4; c += 32) {
            float4 a = Kr[c], b = vv[c];
            sum = fmaf(a.x, b.x, fmaf(a.y, b.y, fmaf(a.z, b.z, fmaf(a.w, b.w, sum))));
        }
#pragma unroll
        for (int o = 16; o; o >>= 1) sum += __shfl_xor_sync(0xffffffffu, sum, o);
        if (lane == 0) out[row] = sum;
    }
    // total gbar calls: 2 + 2*ITER (even) -> d_flag/d_rel return to 0 for next replay
}

// ---------------- launch ----------------
extern "C" void kernel_launch(void* const* d_in, const int* in_sizes, int n_in,
                              void* d_out, int out_size) {
    const float* Xtr = (const float*)d_in[0];
    const float* ytr = (const float*)d_in[1];
    const float* Xte = (const float*)d_in[2];
    mega_kernel<<<GRID, BLOCK>>>(Xtr, ytr, Xte, (float*)d_out);
}

// round 6
// speedup vs baseline: 3.0002x; 1.1489x over previous
#include <cuda_runtime.h>
#include <math.h>

#define N      4096
#define DIMS   8
#define REGL   1e-3f
#define ITER   36
#define GRID   128
#define BLOCK  512
#define RPB    (N / GRID)        // 32 rows owned per block
#define NWARP  (BLOCK / 32)      // 16
#define VPT    (N / 4 / BLOCK)   // 2 float4 per thread in vector ops

// ---------------- device scratch (no allocations allowed) ----------------
__device__ float4 d_ftr[DIMS * N];        // train features: (x, cos(x/2), sin(x/2), 0)
__device__ float  d_ntr[N];
__device__ float4 d_fte[DIMS * N];
__device__ float  d_nte[N];
__device__ float  d_A [(size_t)N * N];    // K_train + reg*I   (64 MB)
__device__ float  d_x[N], d_q[N];
__device__ float  d_ppq[GRID];

// ---------------- flag-tree grid barrier (sense-reversing, R5-proven) ----------------
__device__ volatile unsigned d_flag[GRID];
__device__ volatile unsigned d_rel;

__device__ __forceinline__ void gbar(unsigned* lsense) {
    const unsigned s = *lsense ^ 1u;
    *lsense = s;
    __syncthreads();
    if (blockIdx.x == 0) {
        __threadfence();
        const int t = threadIdx.x;
        if (t >= 1 && t < GRID) { while (d_flag[t] != s) { } }
        __syncthreads();
        if (t == 0) { __threadfence(); d_rel = s; }
        __threadfence();
    } else {
        if (threadIdx.x == 0) {
            __threadfence();
            d_flag[blockIdx.x] = s;
            while (d_rel != s) { }
            __threadfence();
        }
    }
    __syncthreads();
}

// ---------------- the whole pipeline in one persistent kernel ----------------
__global__ __launch_bounds__(BLOCK)
void mega_kernel(const float* __restrict__ Xtr, const float* __restrict__ ytr,
                 const float* __restrict__ Xte, float* __restrict__ out) {
    __shared__ __align__(16) float s_p[N];   // 16 KB: full p (identical in all blocks); x at predict
    __shared__ __align__(16) float s_r[N];   // 16 KB: full r
    __shared__ float4 s_tf[DIMS][32];
    __shared__ float  s_tn[32];
    __shared__ float  s_red[NWARP];
    __shared__ float  s_part[NWARP * 32];    // predict: per-warp row partials
    __shared__ float  s_bc[2];

    unsigned lsense = 0;
    const int tid = threadIdx.x, blk = blockIdx.x;
    const int warp = tid >> 5, lane = tid & 31;

    // ===== Phase A: per-point features =====
    for (int i = blk * BLOCK + tid; i < 2 * N; i += GRID * BLOCK) {
        const int   j  = (i < N) ? i : i - N;
        const float* X = (i < N) ? Xtr : Xte;
        float4* fd = (i < N) ? d_ftr : d_fte;
        float*  fn = (i < N) ? d_ntr : d_nte;
        float nrm = 0.f;
#pragma unroll
        for (int d = 0; d < DIMS; d++) {
            float v = X[j * DIMS + d];
            nrm = fmaf(v, v, nrm);
            float s, c;
            __sincosf(0.5f * v, &s, &c);
            fd[d * N + j] = make_float4(v, c, s, 0.f);
        }
        fn[j] = nrm;
    }
    if (tid < RPB) d_x[blk * RPB + tid] = 0.f;
    gbar(&lsense);                                                   // bar #1

    // ===== Phase B: build A only; 32-row x 512-col tiles (8 tiles per block) =====
    for (int t = blk; t < 1024; t += GRID) {
        const int rowT = t >> 3, colT = t & 7;

        for (int k = tid; k < 32 * DIMS; k += BLOCK) {
            int d = k >> 5, rr = k & 31;
            s_tf[d][rr] = d_ftr[d * N + rowT * 32 + rr];
        }
        if (tid < 32) s_tn[tid] = d_ntr[rowT * 32 + tid];
        __syncthreads();

        const int col = colT * 512 + tid;
        float4 cf[DIMS];
#pragma unroll
        for (int d = 0; d < DIMS; d++) cf[d] = d_ftr[d * N + col];
        const float cn = d_ntr[col];

#pragma unroll 4
        for (int rr = 0; rr < 32; rr++) {
            float dot = 0.f, prod = 1.f;
#pragma unroll
            for (int d = 0; d < DIMS; d++) {
                float4 rf = s_tf[d][rr];
                dot  = fmaf(rf.x, cf[d].x, dot);
                prod *= fmaf(rf.z, cf[d].z, rf.y * cf[d].y);
            }
            float sq  = s_tn[rr] + cn - 2.f * dot;
            float val = __expf(-sq) * fabsf(prod);
            int row = rowT * 32 + rr;
            if (row == col) val += REGL;
            d_A[(size_t)row * N + col] = val;
        }
        __syncthreads();
    }

    // ===== CG init: r = p = y in smem (every block), rs = y.y (identical per block) =====
    float part = 0.f;
    for (int i = tid; i < N; i += BLOCK) {
        float v = ytr[i];
        s_r[i] = v; s_p[i] = v;
        part = fmaf(v, v, part);
    }
#pragma unroll
    for (int o = 16; o; o >>= 1) part += __shfl_xor_sync(0xffffffffu, part, o);
    if (lane == 0) s_red[warp] = part;
    __syncthreads();
    if (tid == 0) {
        float s = 0.f;
        for (int k = 0; k < NWARP; k++) s += s_red[k];
        s_bc[0] = s;
    }
    __syncthreads();
    float rs = s_bc[0];
    gbar(&lsense);                                                   // bar #2 (covers build)

    // ===== CG loop: 2 barriers per iteration =====
    for (int it = 0; it < ITER; it++) {
        // --- q[own 2 rows/warp] = A * p, interleaved (p loaded once, 4 FMA chains) ---
        const int r0 = blk * RPB + warp * 2;
        {
            const float4* A0 = (const float4*)(d_A + (size_t)r0 * N);
            const float4* A1 = (const float4*)(d_A + (size_t)(r0 + 1) * N);
            const float4* vv = (const float4*)s_p;
            float s00 = 0.f, s01 = 0.f, s10 = 0.f, s11 = 0.f;
#pragma unroll 8
            for (int c = lane; c < N / 4; c += 32) {
                float4 b  = vv[c];
                float4 a0 = A0[c];
                float4 a1 = A1[c];
                s00 = fmaf(a0.x, b.x, fmaf(a0.y, b.y, s00));
                s01 = fmaf(a0.z, b.z, fmaf(a0.w, b.w, s01));
                s10 = fmaf(a1.x, b.x, fmaf(a1.y, b.y, s10));
                s11 = fmaf(a1.z, b.z, fmaf(a1.w, b.w, s11));
            }
            float sum0 = s00 + s01, sum1 = s10 + s11;
#pragma unroll
            for (int o = 16; o; o >>= 1) {
                sum0 += __shfl_xor_sync(0xffffffffu, sum0, o);
                sum1 += __shfl_xor_sync(0xffffffffu, sum1, o);
            }
            if (lane == 0) {
                d_q[r0]     = sum0;
                d_q[r0 + 1] = sum1;
                s_red[warp] = fmaf(sum0, s_p[r0], sum1 * s_p[r0 + 1]);
            }
        }
        __syncthreads();
        if (tid == 0) {
            float s = 0.f;
            for (int k = 0; k < NWARP; k++) s += s_red[k];
            d_ppq[blk] = s;
        }
        gbar(&lsense);                                               // bar (2k+3): q + partials ready

        // --- pAp: every block reduces the 128 partials identically ---
        if (tid < GRID) {
            float v = __ldcg((const float*)&d_ppq[tid]);
#pragma unroll
            for (int o = 16; o; o >>= 1) v += __shfl_xor_sync(0xffffffffu, v, o);
            if (lane == 0) s_red[warp] = v;
        }
        __syncthreads();
        if (tid == 0) s_bc[1] = ((s_red[0] + s_red[1]) + (s_red[2] + s_red[3]));
        __syncthreads();
        const float pAp   = s_bc[1];
        const float alpha = (pAp > 0.f && rs > 0.f) ? rs / pAp : 0.f;

        // --- full r update (redundant per block, identical) + block-local rr ---
        float rrp = 0.f;
#pragma unroll
        for (int k = 0; k < VPT; k++) {
            const int i = tid + k * BLOCK;
            float4 qv = __ldcg(((const float4*)d_q) + i);
            float4 rv = ((float4*)s_r)[i];
            rv.x = fmaf(-alpha, qv.x, rv.x);
            rv.y = fmaf(-alpha, qv.y, rv.y);
            rv.z = fmaf(-alpha, qv.z, rv.z);
            rv.w = fmaf(-alpha, qv.w, rv.w);
            ((float4*)s_r)[i] = rv;
            rrp = fmaf(rv.x, rv.x, fmaf(rv.y, rv.y, fmaf(rv.z, rv.z, fmaf(rv.w, rv.w, rrp))));
        }
        // x update: own rows only
        if (tid < RPB) {
            int e = blk * RPB + tid;
            d_x[e] = fmaf(alpha, s_p[e], d_x[e]);
        }
#pragma unroll
        for (int o = 16; o; o >>= 1) rrp += __shfl_xor_sync(0xffffffffu, rrp, o);
        if (lane == 0) s_red[warp] = rrp;
        __syncthreads();
        if (tid == 0) {
            float s = 0.f;
            for (int k = 0; k < NWARP; k++) s += s_red[k];
            s_bc[0] = s;
        }
        __syncthreads();
        const float rsnew = s_bc[0];
        const float beta  = (rs > 0.f) ? rsnew / rs : 0.f;
        rs = rsnew;

        // --- full p update (redundant per block, identical) ---
#pragma unroll
        for (int k = 0; k < VPT; k++) {
            const int i = tid + k * BLOCK;
            float4 pv = ((float4*)s_p)[i];
            float4 rv = ((float4*)s_r)[i];
            pv.x = fmaf(beta, pv.x, rv.x);
            pv.y = fmaf(beta, pv.y, rv.y);
            pv.z = fmaf(beta, pv.z, rv.z);
            pv.w = fmaf(beta, pv.w, rv.w);
            ((float4*)s_p)[i] = pv;
        }
        gbar(&lsense);                                               // bar (2k+4)
    }

    // ===== Predict (fused): y_pred[own 32 test rows] = K(test_rows, :) @ x, on the fly =====
    // x -> s_p (full copy per block)
#pragma unroll
    for (int k = 0; k < VPT; k++) {
        const int i = tid + k * BLOCK;
        ((float4*)s_p)[i] = __ldcg(((const float4*)d_x) + i);
    }
    // test-row features for this block's 32 rows -> s_tf
    for (int k = tid; k < 32 * DIMS; k += BLOCK) {
        int d = k >> 5, rr = k & 31;
        s_tf[d][rr] = d_fte[d * N + blk * 32 + rr];
    }
    if (tid < 32) s_tn[tid] = d_nte[blk * 32 + tid];
    __syncthreads();

    float acc[32];
#pragma unroll
    for (int rr = 0; rr < 32; rr++) acc[rr] = 0.f;

    for (int ct = 0; ct < 8; ct++) {
        const int col = ct * 512 + tid;
        float4 cf[DIMS];
#pragma unroll
        for (int d = 0; d < DIMS; d++) cf[d] = d_ftr[d * N + col];
        const float cn = d_ntr[col];
        const float xv = s_p[col];

#pragma unroll 4
        for (int rr = 0; rr < 32; rr++) {
            float dot = 0.f, prod = 1.f;
#pragma unroll
            for (int d = 0; d < DIMS; d++) {
                float4 rf = s_tf[d][rr];
                dot  = fmaf(rf.x, cf[d].x, dot);
                prod *= fmaf(rf.z, cf[d].z, rf.y * cf[d].y);
            }
            float sq  = s_tn[rr] + cn - 2.f * dot;
            acc[rr] = fmaf(__expf(-sq) * fabsf(prod), xv, acc[rr]);
        }
    }
    // reduce acc across the block: warp-level shuffles, then cross-warp
#pragma unroll
    for (int rr = 0; rr < 32; rr++) {
        float v = acc[rr];
#pragma unroll
        for (int o = 16; o; o >>= 1) v += __shfl_xor_sync(0xffffffffu, v, o);
        if (lane == 0) s_part[warp * 32 + rr] = v;
    }
    __syncthreads();
    if (tid < 32) {
        float s = 0.f;
#pragma unroll
        for (int w = 0; w < NWARP; w++) s += s_part[w * 32 + tid];
        out[blk * 32 + tid] = s;
    }
    // total gbar calls: 2 + 2*ITER (even) -> d_flag/d_rel return to 0 for next replay
}

// ---------------- launch ----------------
extern "C" void kernel_launch(void* const* d_in, const int* in_sizes, int n_in,
                              void* d_out, int out_size) {
    const float* Xtr = (const float*)d_in[0];
    const float* ytr = (const float*)d_in[1];
    const float* Xte = (const float*)d_in[2];
    mega_kernel<<<GRID, BLOCK>>>(Xtr, ytr, Xte, (float*)d_out);
}

// round 7
// speedup vs baseline: 3.0683x; 1.0227x over previous
#include <cuda_runtime.h>
#include <math.h>

#define N      4096
#define DIMS   8
#define REGL   1e-3f
#define ITER   36
#define GRID   256
#define BLOCK  512
#define RPB    (N / GRID)        // 16 rows owned per block
#define NWARP  (BLOCK / 32)      // 16
#define VPT    (N / 4 / BLOCK)   // 2 float4 per thread in vector ops

// ---------------- device scratch (no allocations allowed) ----------------
__device__ float4 d_ftr[DIMS * N];        // train features: (x, cos(x/2), sin(x/2), 0)
__device__ float  d_ntr[N];
__device__ float4 d_fte[DIMS * N];
__device__ float  d_nte[N];
__device__ float  d_A [(size_t)N * N];    // K_train + reg*I   (64 MB)
__device__ float  d_x[N], d_q[N];
__device__ float  d_ppq[GRID];

// ---------------- flag-tree grid barrier (sense-reversing, R5-proven) ----------------
__device__ volatile unsigned d_flag[GRID];
__device__ volatile unsigned d_rel;

__device__ __forceinline__ void gbar(unsigned* lsense) {
    const unsigned s = *lsense ^ 1u;
    *lsense = s;
    __syncthreads();
    if (blockIdx.x == 0) {
        __threadfence();
        const int t = threadIdx.x;
        if (t >= 1 && t < GRID) { while (d_flag[t] != s) { } }
        __syncthreads();
        if (t == 0) { __threadfence(); d_rel = s; }
        __threadfence();
    } else {
        if (threadIdx.x == 0) {
            __threadfence();
            d_flag[blockIdx.x] = s;
            while (d_rel != s) { }
            __threadfence();
        }
    }
    __syncthreads();
}

// ---------------- the whole pipeline in one persistent kernel ----------------
__global__ __launch_bounds__(BLOCK, 2)
void mega_kernel(const float* __restrict__ Xtr, const float* __restrict__ ytr,
                 const float* __restrict__ Xte, float* __restrict__ out) {
    __shared__ __align__(16) float s_p[N];   // 16 KB: full p (identical in all blocks); x at predict
    __shared__ __align__(16) float s_r[N];   // 16 KB: full r
    __shared__ float4 s_tf[DIMS][32];
    __shared__ float  s_tn[32];
    __shared__ float  s_red[NWARP];
    __shared__ float  s_part[NWARP * RPB];   // predict: per-warp row partials
    __shared__ float  s_bc[2];

    unsigned lsense = 0;
    const int tid = threadIdx.x, blk = blockIdx.x;
    const int warp = tid >> 5, lane = tid & 31;

    // ===== Phase A: per-point features =====
    for (int i = blk * BLOCK + tid; i < 2 * N; i += GRID * BLOCK) {
        const int   j  = (i < N) ? i : i - N;
        const float* X = (i < N) ? Xtr : Xte;
        float4* fd = (i < N) ? d_ftr : d_fte;
        float*  fn = (i < N) ? d_ntr : d_nte;
        float nrm = 0.f;
#pragma unroll
        for (int d = 0; d < DIMS; d++) {
            float v = X[j * DIMS + d];
            nrm = fmaf(v, v, nrm);
            float s, c;
            __sincosf(0.5f * v, &s, &c);
            fd[d * N + j] = make_float4(v, c, s, 0.f);
        }
        fn[j] = nrm;
    }
    if (tid < RPB) d_x[blk * RPB + tid] = 0.f;
    gbar(&lsense);                                                   // bar #1

    // ===== Phase B: build A; 32-row x 512-col tiles (4 tiles per block) =====
    for (int t = blk; t < 1024; t += GRID) {
        const int rowT = t >> 3, colT = t & 7;

        for (int k = tid; k < 32 * DIMS; k += BLOCK) {
            int d = k >> 5, rr = k & 31;
            s_tf[d][rr] = d_ftr[d * N + rowT * 32 + rr];
        }
        if (tid < 32) s_tn[tid] = d_ntr[rowT * 32 + tid];
        __syncthreads();

        const int col = colT * 512 + tid;
        float4 cf[DIMS];
#pragma unroll
        for (int d = 0; d < DIMS; d++) cf[d] = d_ftr[d * N + col];
        const float cn = d_ntr[col];

#pragma unroll 4
        for (int rr = 0; rr < 32; rr++) {
            float dot = 0.f, prod = 1.f;
#pragma unroll
            for (int d = 0; d < DIMS; d++) {
                float4 rf = s_tf[d][rr];
                dot  = fmaf(rf.x, cf[d].x, dot);
                prod *= fmaf(rf.z, cf[d].z, rf.y * cf[d].y);
            }
            float sq  = s_tn[rr] + cn - 2.f * dot;
            float val = __expf(-sq) * fabsf(prod);
            int row = rowT * 32 + rr;
            if (row == col) val += REGL;
            d_A[(size_t)row * N + col] = val;
        }
        __syncthreads();
    }

    // ===== CG init: r = p = y in smem (every block), rs = y.y (identical per block) =====
    float part = 0.f;
    for (int i = tid; i < N; i += BLOCK) {
        float v = ytr[i];
        s_r[i] = v; s_p[i] = v;
        part = fmaf(v, v, part);
    }
#pragma unroll
    for (int o = 16; o; o >>= 1) part += __shfl_xor_sync(0xffffffffu, part, o);
    if (lane == 0) s_red[warp] = part;
    __syncthreads();
    if (tid == 0) {
        float s = 0.f;
        for (int k = 0; k < NWARP; k++) s += s_red[k];
        s_bc[0] = s;
    }
    __syncthreads();
    float rs = s_bc[0];
    gbar(&lsense);                                                   // bar #2 (covers build)

    // ===== CG loop: 2 barriers per iteration =====
    for (int it = 0; it < ITER; it++) {
        // --- q[own row per warp] = A * p, 4 independent FMA chains ---
        const int row = blk * RPB + warp;
        {
            const float4* Ar = (const float4*)(d_A + (size_t)row * N);
            const float4* vv = (const float4*)s_p;
            float s0 = 0.f, s1 = 0.f, s2 = 0.f, s3 = 0.f;
#pragma unroll 8
            for (int c = lane; c < N / 4; c += 32) {
                float4 a = Ar[c], b = vv[c];
                s0 = fmaf(a.x, b.x, s0);
                s1 = fmaf(a.y, b.y, s1);
                s2 = fmaf(a.z, b.z, s2);
                s3 = fmaf(a.w, b.w, s3);
            }
            float sum = (s0 + s1) + (s2 + s3);
#pragma unroll
            for (int o = 16; o; o >>= 1) sum += __shfl_xor_sync(0xffffffffu, sum, o);
            if (lane == 0) {
                d_q[row] = sum;
                s_red[warp] = sum * s_p[row];
            }
        }
        __syncthreads();
        if (tid == 0) {
            float s = 0.f;
            for (int k = 0; k < NWARP; k++) s += s_red[k];
            d_ppq[blk] = s;
        }
        gbar(&lsense);                                               // bar (2k+3): q + partials ready

        // --- pAp: every block reduces the 256 partials identically ---
        if (tid < GRID) {
            float v = __ldcg((const float*)&d_ppq[tid]);
#pragma unroll
            for (int o = 16; o; o >>= 1) v += __shfl_xor_sync(0xffffffffu, v, o);
            if (lane == 0) s_red[warp] = v;
        }
        __syncthreads();
        if (tid == 0) {
            float s = 0.f;
#pragma unroll
            for (int k = 0; k < GRID / 32; k++) s += s_red[k];
            s_bc[1] = s;
        }
        __syncthreads();
        const float pAp   = s_bc[1];
        const float alpha = (pAp > 0.f && rs > 0.f) ? rs / pAp : 0.f;

        // --- full r update (redundant per block, identical) + block-local rr ---
        float rrp = 0.f;
#pragma unroll
        for (int k = 0; k < VPT; k++) {
            const int i = tid + k * BLOCK;
            float4 qv = __ldcg(((const float4*)d_q) + i);
            float4 rv = ((float4*)s_r)[i];
            rv.x = fmaf(-alpha, qv.x, rv.x);
            rv.y = fmaf(-alpha, qv.y, rv.y);
            rv.z = fmaf(-alpha, qv.z, rv.z);
            rv.w = fmaf(-alpha, qv.w, rv.w);
            ((float4*)s_r)[i] = rv;
            rrp = fmaf(rv.x, rv.x, fmaf(rv.y, rv.y, fmaf(rv.z, rv.z, fmaf(rv.w, rv.w, rrp))));
        }
        // x update: own rows only
        if (tid < RPB) {
            int e = blk * RPB + tid;
            d_x[e] = fmaf(alpha, s_p[e], d_x[e]);
        }
#pragma unroll
        for (int o = 16; o; o >>= 1) rrp += __shfl_xor_sync(0xffffffffu, rrp, o);
        if (lane == 0) s_red[warp] = rrp;
        __syncthreads();
        if (tid == 0) {
            float s = 0.f;
            for (int k = 0; k < NWARP; k++) s += s_red[k];
            s_bc[0] = s;
        }
        __syncthreads();
        const float rsnew = s_bc[0];
        const float beta  = (rs > 0.f) ? rsnew / rs : 0.f;
        rs = rsnew;

        // --- full p update (redundant per block, identical) ---
#pragma unroll
        for (int k = 0; k < VPT; k++) {
            const int i = tid + k * BLOCK;
            float4 pv = ((float4*)s_p)[i];
            float4 rv = ((float4*)s_r)[i];
            pv.x = fmaf(beta, pv.x, rv.x);
            pv.y = fmaf(beta, pv.y, rv.y);
            pv.z = fmaf(beta, pv.z, rv.z);
            pv.w = fmaf(beta, pv.w, rv.w);
            ((float4*)s_p)[i] = pv;
        }
        gbar(&lsense);                                               // bar (2k+4)
    }

    // ===== Predict (fused): y_pred[own RPB test rows] = K(test_rows, :) @ x, on the fly =====
#pragma unroll
    for (int k = 0; k < VPT; k++) {
        const int i = tid + k * BLOCK;
        ((float4*)s_p)[i] = __ldcg(((const float4*)d_x) + i);
    }
    for (int k = tid; k < RPB * DIMS; k += BLOCK) {
        int d = k >> 4, rr = k & (RPB - 1);
        s_tf[d][rr] = d_fte[d * N + blk * RPB + rr];
    }
    if (tid < RPB) s_tn[tid] = d_nte[blk * RPB + tid];
    __syncthreads();

    float acc[RPB];
#pragma unroll
    for (int rr = 0; rr < RPB; rr++) acc[rr] = 0.f;

    for (int ct = 0; ct < 8; ct++) {
        const int col = ct * 512 + tid;
        float4 cf[DIMS];
#pragma unroll
        for (int d = 0; d < DIMS; d++) cf[d] = d_ftr[d * N + col];
        const float cn = d_ntr[col];
        const float xv = s_p[col];

#pragma unroll 4
        for (int rr = 0; rr < RPB; rr++) {
            float dot = 0.f, prod = 1.f;
#pragma unroll
            for (int d = 0; d < DIMS; d++) {
                float4 rf = s_tf[d][rr];
                dot  = fmaf(rf.x, cf[d].x, dot);
                prod *= fmaf(rf.z, cf[d].z, rf.y * cf[d].y);
            }
            float sq  = s_tn[rr] + cn - 2.f * dot;
            acc[rr] = fmaf(__expf(-sq) * fabsf(prod), xv, acc[rr]);
        }
    }
#pragma unroll
    for (int rr = 0; rr < RPB; rr++) {
        float v = acc[rr];
#pragma unroll
        for (int o = 16; o; o >>= 1) v += __shfl_xor_sync(0xffffffffu, v, o);
        if (lane == 0) s_part[warp * RPB + rr] = v;
    }
    __syncthreads();
    if (tid < RPB) {
        float s = 0.f;
#pragma unroll
        for (int w = 0; w < NWARP; w++) s += s_part[w * RPB + tid];
        out[blk * RPB + tid] = s;
    }
    // total gbar calls: 2 + 2*ITER (even) -> d_flag/d_rel return to 0 for next replay
}

// ---------------- launch ----------------
extern "C" void kernel_launch(void* const* d_in, const int* in_sizes, int n_in,
                              void* d_out, int out_size) {
    const float* Xtr = (const float*)d_in[0];
    const float* ytr = (const float*)d_in[1];
    const float* Xte = (const float*)d_in[2];
    mega_kernel<<<GRID, BLOCK>>>(Xtr, ytr, Xte, (float*)d_out);
}

// round 8
// speedup vs baseline: 3.6170x; 1.1788x over previous
#include <cuda_runtime.h>
#include <math.h>

#define N      4096
#define DIMS   8
#define REGL   1e-3f
#define ITER   35                // total gbars = 2 + ITER + 1 = 38 (even -> replay-safe)
#define GRID   256
#define BLOCK  512
#define RPB    (N / GRID)        // 16 rows owned per block
#define NWARP  (BLOCK / 32)      // 16
#define VPT    (N / 4 / BLOCK)   // 2 float4 per thread in vector ops

// ---------------- device scratch (no allocations allowed) ----------------
__device__ float4 d_ftr[DIMS * N];        // train features: (x, cos(x/2), sin(x/2), 0)
__device__ float  d_ntr[N];
__device__ float4 d_fte[DIMS * N];
__device__ float  d_nte[N];
__device__ float  d_A [(size_t)N * N];    // K_train + reg*I   (64 MB)
__device__ float  d_x[N];
__device__ float  d_q0[N], d_q1[N];       // double-buffered A*p

// ---------------- flag-tree grid barrier (sense-reversing, R5-proven) ----------------
__device__ volatile unsigned d_flag[GRID];
__device__ volatile unsigned d_rel;

__device__ __forceinline__ void gbar(unsigned* lsense) {
    const unsigned s = *lsense ^ 1u;
    *lsense = s;
    __syncthreads();
    if (blockIdx.x == 0) {
        __threadfence();
        const int t = threadIdx.x;
        if (t >= 1 && t < GRID) { while (d_flag[t] != s) { } }
        __syncthreads();
        if (t == 0) { __threadfence(); d_rel = s; }
        __threadfence();
    } else {
        if (threadIdx.x == 0) {
            __threadfence();
            d_flag[blockIdx.x] = s;
            while (d_rel != s) { }
            __threadfence();
        }
    }
    __syncthreads();
}

// block reduce: warp partials -> s_red, warp0 shuffle-combines, result in s_bc[slot]
__device__ __forceinline__ float block_sum(float v, float* s_red, float* s_bc, int slot) {
    const int warp = threadIdx.x >> 5, lane = threadIdx.x & 31;
#pragma unroll
    for (int o = 16; o; o >>= 1) v += __shfl_xor_sync(0xffffffffu, v, o);
    if (lane == 0) s_red[warp] = v;
    __syncthreads();
    if (warp == 0) {
        float t = (lane < NWARP) ? s_red[lane] : 0.f;
#pragma unroll
        for (int o = 8; o; o >>= 1) t += __shfl_xor_sync(0xffffffffu, t, o);
        if (lane == 0) s_bc[slot] = t;
    }
    __syncthreads();
    return s_bc[slot];
}

// ---------------- the whole pipeline in one persistent kernel ----------------
__global__ __launch_bounds__(BLOCK, 2)
void mega_kernel(const float* __restrict__ Xtr, const float* __restrict__ ytr,
                 const float* __restrict__ Xte, float* __restrict__ out) {
    __shared__ __align__(16) float s_p[N];   // 16 KB: full p (identical in all blocks); x at predict
    __shared__ __align__(16) float s_r[N];   // 16 KB: full r
    __shared__ float4 s_tf[DIMS][32];
    __shared__ float  s_tn[32];
    __shared__ float  s_red[NWARP];
    __shared__ float  s_part[NWARP * RPB];   // predict: per-warp row partials
    __shared__ float  s_bc[2];

    unsigned lsense = 0;
    const int tid = threadIdx.x, blk = blockIdx.x;
    const int warp = tid >> 5, lane = tid & 31;

    // ===== Phase A: per-point features =====
    for (int i = blk * BLOCK + tid; i < 2 * N; i += GRID * BLOCK) {
        const int   j  = (i < N) ? i : i - N;
        const float* X = (i < N) ? Xtr : Xte;
        float4* fd = (i < N) ? d_ftr : d_fte;
        float*  fn = (i < N) ? d_ntr : d_nte;
        float nrm = 0.f;
#pragma unroll
        for (int d = 0; d < DIMS; d++) {
            float v = X[j * DIMS + d];
            nrm = fmaf(v, v, nrm);
            float s, c;
            __sincosf(0.5f * v, &s, &c);
            fd[d * N + j] = make_float4(v, c, s, 0.f);
        }
        fn[j] = nrm;
    }
    if (tid < RPB) d_x[blk * RPB + tid] = 0.f;
    gbar(&lsense);                                                   // bar 1

    // ===== Phase B: build A; 32-row x 512-col tiles (4 tiles per block) =====
    for (int t = blk; t < 1024; t += GRID) {
        const int rowT = t >> 3, colT = t & 7;

        for (int k = tid; k < 32 * DIMS; k += BLOCK) {
            int d = k >> 5, rr = k & 31;
            s_tf[d][rr] = d_ftr[d * N + rowT * 32 + rr];
        }
        if (tid < 32) s_tn[tid] = d_ntr[rowT * 32 + tid];
        __syncthreads();

        const int col = colT * 512 + tid;
        float4 cf[DIMS];
#pragma unroll
        for (int d = 0; d < DIMS; d++) cf[d] = d_ftr[d * N + col];
        const float cn = d_ntr[col];

#pragma unroll 4
        for (int rr = 0; rr < 32; rr++) {
            float dot = 0.f, prod = 1.f;
#pragma unroll
            for (int d = 0; d < DIMS; d++) {
                float4 rf = s_tf[d][rr];
                dot  = fmaf(rf.x, cf[d].x, dot);
                prod *= fmaf(rf.z, cf[d].z, rf.y * cf[d].y);
            }
            float sq  = s_tn[rr] + cn - 2.f * dot;
            float val = __expf(-sq) * fabsf(prod);
            int row = rowT * 32 + rr;
            if (row == col) val += REGL;
            d_A[(size_t)row * N + col] = val;
        }
        __syncthreads();
    }

    // ===== CG init: r = p = y in smem (every block), rs = y.y (identical per block) =====
    float part = 0.f;
    for (int i = tid; i < N; i += BLOCK) {
        float v = ytr[i];
        s_r[i] = v; s_p[i] = v;
        part = fmaf(v, v, part);
    }
    float rs = block_sum(part, s_red, s_bc, 0);
    gbar(&lsense);                                                   // bar 2 (covers build)

    // ===== CG loop: ONE barrier per iteration (double-buffered q) =====
    for (int it = 0; it < ITER; it++) {
        float* qb = (it & 1) ? d_q1 : d_q0;

        // --- q[own row per warp] = A * p, 4 independent FMA chains, A streamed via L2 ---
        const int row = blk * RPB + warp;
        {
            const float4* Ar = (const float4*)(d_A + (size_t)row * N);
            const float4* vv = (const float4*)s_p;
            float s0 = 0.f, s1 = 0.f, s2 = 0.f, s3 = 0.f;
#pragma unroll 8
            for (int c = lane; c < N / 4; c += 32) {
                float4 a = __ldcg(Ar + c);
                float4 b = vv[c];
                s0 = fmaf(a.x, b.x, s0);
                s1 = fmaf(a.y, b.y, s1);
                s2 = fmaf(a.z, b.z, s2);
                s3 = fmaf(a.w, b.w, s3);
            }
            float sum = (s0 + s1) + (s2 + s3);
#pragma unroll
            for (int o = 16; o; o >>= 1) sum += __shfl_xor_sync(0xffffffffu, sum, o);
            if (lane == 0) qb[row] = sum;
        }
        gbar(&lsense);                                               // bar (it+3): all q visible

        // --- pass 1: load full q (cache in regs), pAp block-locally (identical everywhere) ---
        float4 qv[VPT];
        float pq = 0.f;
#pragma unroll
        for (int k = 0; k < VPT; k++) {
            const int i = tid + k * BLOCK;
            qv[k] = __ldcg(((const float4*)qb) + i);
            float4 pv = ((const float4*)s_p)[i];
            pq = fmaf(qv[k].x, pv.x, fmaf(qv[k].y, pv.y,
                 fmaf(qv[k].z, pv.z, fmaf(qv[k].w, pv.w, pq))));
        }
        const float pAp   = block_sum(pq, s_red, s_bc, 1);
        const float alpha = (pAp > 0.f && rs > 0.f) ? rs / pAp : 0.f;

        // --- pass 2: r -= alpha*q (smem), rr partial; x own rows ---
        float rrp = 0.f;
#pragma unroll
        for (int k = 0; k < VPT; k++) {
            const int i = tid + k * BLOCK;
            float4 rv = ((float4*)s_r)[i];
            rv.x = fmaf(-alpha, qv[k].x, rv.x);
            rv.y = fmaf(-alpha, qv[k].y, rv.y);
            rv.z = fmaf(-alpha, qv[k].z, rv.z);
            rv.w = fmaf(-alpha, qv[k].w, rv.w);
            ((float4*)s_r)[i] = rv;
            rrp = fmaf(rv.x, rv.x, fmaf(rv.y, rv.y, fmaf(rv.z, rv.z, fmaf(rv.w, rv.w, rrp))));
        }
        if (tid < RPB) {
            int e = blk * RPB + tid;
            d_x[e] = fmaf(alpha, s_p[e], d_x[e]);
        }
        const float rsnew = block_sum(rrp, s_red, s_bc, 0);
        const float beta  = (rs > 0.f) ? rsnew / rs : 0.f;
        rs = rsnew;

        // --- pass 3: p = r + beta*p ---
#pragma unroll
        for (int k = 0; k < VPT; k++) {
            const int i = tid + k * BLOCK;
            float4 pv = ((float4*)s_p)[i];
            float4 rv = ((float4*)s_r)[i];
            pv.x = fmaf(beta, pv.x, rv.x);
            pv.y = fmaf(beta, pv.y, rv.y);
            pv.z = fmaf(beta, pv.z, rv.z);
            pv.w = fmaf(beta, pv.w, rv.w);
            ((float4*)s_p)[i] = pv;
        }
        __syncthreads();
    }
    gbar(&lsense);                                                   // bar (ITER+3): x complete

    // ===== Predict (fused): y_pred[own RPB test rows] = K(test_rows, :) @ x, on the fly =====
#pragma unroll
    for (int k = 0; k < VPT; k++) {
        const int i = tid + k * BLOCK;
        ((float4*)s_p)[i] = __ldcg(((const float4*)d_x) + i);
    }
    for (int k = tid; k < RPB * DIMS; k += BLOCK) {
        int d = k >> 4, rr = k & (RPB - 1);
        s_tf[d][rr] = d_fte[d * N + blk * RPB + rr];
    }
    if (tid < RPB) s_tn[tid] = d_nte[blk * RPB + tid];
    __syncthreads();

    float acc[RPB];
#pragma unroll
    for (int rr = 0; rr < RPB; rr++) acc[rr] = 0.f;

    for (int ct = 0; ct < 8; ct++) {
        const int col = ct * 512 + tid;
        float4 cf[DIMS];
#pragma unroll
        for (int d = 0; d < DIMS; d++) cf[d] = d_ftr[d * N + col];
        const float cn = d_ntr[col];
        const float xv = s_p[col];

#pragma unroll 4
        for (int rr = 0; rr < RPB; rr++) {
            float dot = 0.f, prod = 1.f;
#pragma unroll
            for (int d = 0; d < DIMS; d++) {
                float4 rf = s_tf[d][rr];
                dot  = fmaf(rf.x, cf[d].x, dot);
                prod *= fmaf(rf.z, cf[d].z, rf.y * cf[d].y);
            }
            float sq  = s_tn[rr] + cn - 2.f * dot;
            acc[rr] = fmaf(__expf(-sq) * fabsf(prod), xv, acc[rr]);
        }
    }
#pragma unroll
    for (int rr = 0; rr < RPB; rr++) {
        float v = acc[rr];
#pragma unroll
        for (int o = 16; o; o >>= 1) v += __shfl_xor_sync(0xffffffffu, v, o);
        if (lane == 0) s_part[warp * RPB + rr] = v;
    }
    __syncthreads();
    if (tid < RPB) {
        float s = 0.f;
#pragma unroll
        for (int w = 0; w < NWARP; w++) s += s_part[w * RPB + tid];
        out[blk * RPB + tid] = s;
    }
    // total gbar calls: 2 + ITER + 1 = 38 (even) -> d_flag/d_rel return to 0 for next replay
}

// ---------------- launch ----------------
extern "C" void kernel_launch(void* const* d_in, const int* in_sizes, int n_in,
                              void* d_out, int out_size) {
    const float* Xtr = (const float*)d_in[0];
    const float* ytr = (const float*)d_in[1];
    const float* Xte = (const float*)d_in[2];
    mega_kernel<<<GRID, BLOCK>>>(Xtr, ytr, Xte, (float*)d_out);
}

// round 9
// speedup vs baseline: 3.8124x; 1.0540x over previous
#include <cuda_runtime.h>
#include <math.h>

#define N      4096
#define DIMS   8
#define REGL   1e-3f
#define ITER   33                // total gbars = 2 + ITER + 1 = 36 (even -> replay-safe)
#define GRID   256
#define BLOCK  512
#define RPB    (N / GRID)        // 16 rows owned per block
#define NWARP  (BLOCK / 32)      // 16
#define VPT    (N / 4 / BLOCK)   // 2 float4 per thread in vector ops
#define SLICE  (N / NWARP)       // 256 columns per warp in matvec
#define SP     17                // padded stride for s_part

// ---------------- device scratch (no allocations allowed) ----------------
__device__ float4 d_ftr[DIMS * N];        // train features: (x, cos(x/2), sin(x/2), 0)
__device__ float  d_ntr[N];
__device__ float4 d_fte[DIMS * N];
__device__ float  d_nte[N];
__device__ float  d_A [(size_t)N * N];    // K_train + reg*I   (64 MB)
__device__ float  d_x[N];
__device__ float  d_q0[N], d_q1[N];       // double-buffered A*p

// ---------------- flag-tree grid barrier (sense-reversing, R5-proven) ----------------
__device__ volatile unsigned d_flag[GRID];
__device__ volatile unsigned d_rel;

__device__ __forceinline__ void gbar(unsigned* lsense) {
    const unsigned s = *lsense ^ 1u;
    *lsense = s;
    __syncthreads();
    if (blockIdx.x == 0) {
        __threadfence();
        const int t = threadIdx.x;
        if (t >= 1 && t < GRID) { while (d_flag[t] != s) { } }
        __syncthreads();
        if (t == 0) { __threadfence(); d_rel = s; }
        __threadfence();
    } else {
        if (threadIdx.x == 0) {
            __threadfence();
            d_flag[blockIdx.x] = s;
            while (d_rel != s) { }
            __threadfence();
        }
    }
    __syncthreads();
}

// block reduce: warp partials -> s_red, warp0 shuffle-combines, result in s_bc[slot]
__device__ __forceinline__ float block_sum(float v, float* s_red, float* s_bc, int slot) {
    const int warp = threadIdx.x >> 5, lane = threadIdx.x & 31;
#pragma unroll
    for (int o = 16; o; o >>= 1) v += __shfl_xor_sync(0xffffffffu, v, o);
    if (lane == 0) s_red[warp] = v;
    __syncthreads();
    if (warp == 0) {
        float t = (lane < NWARP) ? s_red[lane] : 0.f;
#pragma unroll
        for (int o = 8; o; o >>= 1) t += __shfl_xor_sync(0xffffffffu, t, o);
        if (lane == 0) s_bc[slot] = t;
    }
    __syncthreads();
    return s_bc[slot];
}

// ---------------- the whole pipeline in one persistent kernel ----------------
__global__ __launch_bounds__(BLOCK, 2)
void mega_kernel(const float* __restrict__ Xtr, const float* __restrict__ ytr,
                 const float* __restrict__ Xte, float* __restrict__ out) {
    __shared__ __align__(16) float s_p[N];   // 16 KB: full p (identical in all blocks); x at predict
    __shared__ __align__(16) float s_r[N];   // 16 KB: full r
    __shared__ float4 s_tf[DIMS][32];
    __shared__ float  s_tn[32];
    __shared__ float  s_red[NWARP];
    __shared__ float  s_part[NWARP * SP];    // matvec/predict: per-warp row partials (padded)
    __shared__ float  s_bc[2];

    unsigned lsense = 0;
    const int tid = threadIdx.x, blk = blockIdx.x;
    const int warp = tid >> 5, lane = tid & 31;

    // ===== Phase A: per-point features =====
    for (int i = blk * BLOCK + tid; i < 2 * N; i += GRID * BLOCK) {
        const int   j  = (i < N) ? i : i - N;
        const float* X = (i < N) ? Xtr : Xte;
        float4* fd = (i < N) ? d_ftr : d_fte;
        float*  fn = (i < N) ? d_ntr : d_nte;
        float nrm = 0.f;
#pragma unroll
        for (int d = 0; d < DIMS; d++) {
            float v = X[j * DIMS + d];
            nrm = fmaf(v, v, nrm);
            float s, c;
            __sincosf(0.5f * v, &s, &c);
            fd[d * N + j] = make_float4(v, c, s, 0.f);
        }
        fn[j] = nrm;
    }
    if (tid < RPB) d_x[blk * RPB + tid] = 0.f;
    gbar(&lsense);                                                   // bar 1

    // ===== Phase B: build A; 32-row x 512-col tiles (4 tiles per block) =====
    for (int t = blk; t < 1024; t += GRID) {
        const int rowT = t >> 3, colT = t & 7;

        for (int k = tid; k < 32 * DIMS; k += BLOCK) {
            int d = k >> 5, rr = k & 31;
            s_tf[d][rr] = d_ftr[d * N + rowT * 32 + rr];
        }
        if (tid < 32) s_tn[tid] = d_ntr[rowT * 32 + tid];
        __syncthreads();

        const int col = colT * 512 + tid;
        float4 cf[DIMS];
#pragma unroll
        for (int d = 0; d < DIMS; d++) cf[d] = d_ftr[d * N + col];
        const float cn = d_ntr[col];

#pragma unroll 4
        for (int rr = 0; rr < 32; rr++) {
            float dot = 0.f, prod = 1.f;
#pragma unroll
            for (int d = 0; d < DIMS; d++) {
                float4 rf = s_tf[d][rr];
                dot  = fmaf(rf.x, cf[d].x, dot);
                prod *= fmaf(rf.z, cf[d].z, rf.y * cf[d].y);
            }
            float sq  = s_tn[rr] + cn - 2.f * dot;
            float val = __expf(-sq) * fabsf(prod);
            int row = rowT * 32 + rr;
            if (row == col) val += REGL;
            d_A[(size_t)row * N + col] = val;
        }
        __syncthreads();
    }

    // ===== CG init: r = p = y in smem (every block), rs = y.y (identical per block) =====
    float part = 0.f;
    for (int i = tid; i < N; i += BLOCK) {
        float v = ytr[i];
        s_r[i] = v; s_p[i] = v;
        part = fmaf(v, v, part);
    }
    float rs = block_sum(part, s_red, s_bc, 0);
    gbar(&lsense);                                                   // bar 2 (covers build)

    // ===== CG loop: ONE barrier per iteration (double-buffered q) =====
    for (int it = 0; it < ITER; it++) {
        float* qb = (it & 1) ? d_q1 : d_q0;

        // --- q[16 block rows] = A * p: warp-per-256-col-slice; p slice cached in regs ---
        {
            const float4* pv4 = ((const float4*)s_p) + warp * (SLICE / 4);
            const float4  b0  = pv4[lane];
            const float4  b1  = pv4[lane + 32];
            const float4* Abase = (const float4*)(d_A + (size_t)(blk * RPB) * N)
                                  + warp * (SLICE / 4);
            float accr[RPB];
#pragma unroll
            for (int r = 0; r < RPB; r++) {
                const float4* Ar = Abase + (size_t)r * (N / 4);
                float4 a0 = __ldcg(Ar + lane);
                float4 a1 = __ldcg(Ar + lane + 32);
                float d0 = fmaf(a0.x, b0.x, fmaf(a0.y, b0.y,
                           fmaf(a0.z, b0.z, a0.w * b0.w)));
                float d1 = fmaf(a1.x, b1.x, fmaf(a1.y, b1.y,
                           fmaf(a1.z, b1.z, a1.w * b1.w)));
                accr[r] = d0 + d1;
            }
#pragma unroll
            for (int r = 0; r < RPB; r++) {
                float v = accr[r];
#pragma unroll
                for (int o = 16; o; o >>= 1) v += __shfl_xor_sync(0xffffffffu, v, o);
                if (lane == 0) s_part[warp * SP + r] = v;
            }
        }
        __syncthreads();
        if (tid < RPB) {
            float s = 0.f;
#pragma unroll
            for (int w = 0; w < NWARP; w++) s += s_part[w * SP + tid];
            qb[blk * RPB + tid] = s;
        }
        gbar(&lsense);                                               // bar (it+3): all q visible

        // --- pass 1: load full q (cache in regs), pAp block-locally (identical everywhere) ---
        float4 qv[VPT];
        float pq = 0.f;
#pragma unroll
        for (int k = 0; k < VPT; k++) {
            const int i = tid + k * BLOCK;
            qv[k] = __ldcg(((const float4*)qb) + i);
            float4 pv = ((const float4*)s_p)[i];
            pq = fmaf(qv[k].x, pv.x, fmaf(qv[k].y, pv.y,
                 fmaf(qv[k].z, pv.z, fmaf(qv[k].w, pv.w, pq))));
        }
        const float pAp   = block_sum(pq, s_red, s_bc, 1);
        const float alpha = (pAp > 0.f && rs > 0.f) ? rs / pAp : 0.f;

        // --- pass 2: r -= alpha*q (smem), rr partial; x own rows ---
        float rrp = 0.f;
#pragma unroll
        for (int k = 0; k < VPT; k++) {
            const int i = tid + k * BLOCK;
            float4 rv = ((float4*)s_r)[i];
            rv.x = fmaf(-alpha, qv[k].x, rv.x);
            rv.y = fmaf(-alpha, qv[k].y, rv.y);
            rv.z = fmaf(-alpha, qv[k].z, rv.z);
            rv.w = fmaf(-alpha, qv[k].w, rv.w);
            ((float4*)s_r)[i] = rv;
            rrp = fmaf(rv.x, rv.x, fmaf(rv.y, rv.y, fmaf(rv.z, rv.z, fmaf(rv.w, rv.w, rrp))));
        }
        if (tid < RPB) {
            int e = blk * RPB + tid;
            d_x[e] = fmaf(alpha, s_p[e], d_x[e]);
        }
        const float rsnew = block_sum(rrp, s_red, s_bc, 0);
        const float beta  = (rs > 0.f) ? rsnew / rs : 0.f;
        rs = rsnew;

        // --- pass 3: p = r + beta*p ---
#pragma unroll
        for (int k = 0; k < VPT; k++) {
            const int i = tid + k * BLOCK;
            float4 pv = ((float4*)s_p)[i];
            float4 rv = ((float4*)s_r)[i];
            pv.x = fmaf(beta, pv.x, rv.x);
            pv.y = fmaf(beta, pv.y, rv.y);
            pv.z = fmaf(beta, pv.z, rv.z);
            pv.w = fmaf(beta, pv.w, rv.w);
            ((float4*)s_p)[i] = pv;
        }
        __syncthreads();
    }
    gbar(&lsense);                                                   // bar (ITER+3): x complete

    // ===== Predict (fused): y_pred[own RPB test rows] = K(test_rows, :) @ x, on the fly =====
#pragma unroll
    for (int k = 0; k < VPT; k++) {
        const int i = tid + k * BLOCK;
        ((float4*)s_p)[i] = __ldcg(((const float4*)d_x) + i);
    }
    for (int k = tid; k < RPB * DIMS; k += BLOCK) {
        int d = k >> 4, rr = k & (RPB - 1);
        s_tf[d][rr] = d_fte[d * N + blk * RPB + rr];
    }
    if (tid < RPB) s_tn[tid] = d_nte[blk * RPB + tid];
    __syncthreads();

    float acc[RPB];
#pragma unroll
    for (int rr = 0; rr < RPB; rr++) acc[rr] = 0.f;

    for (int ct = 0; ct < 8; ct++) {
        const int col = ct * 512 + tid;
        float4 cf[DIMS];
#pragma unroll
        for (int d = 0; d < DIMS; d++) cf[d] = d_ftr[d * N + col];
        const float cn = d_ntr[col];
        const float xv = s_p[col];

#pragma unroll 4
        for (int rr = 0; rr < RPB; rr++) {
            float dot = 0.f, prod = 1.f;
#pragma unroll
            for (int d = 0; d < DIMS; d++) {
                float4 rf = s_tf[d][rr];
                dot  = fmaf(rf.x, cf[d].x, dot);
                prod *= fmaf(rf.z, cf[d].z, rf.y * cf[d].y);
            }
            float sq  = s_tn[rr] + cn - 2.f * dot;
            acc[rr] = fmaf(__expf(-sq) * fabsf(prod), xv, acc[rr]);
        }
    }
#pragma unroll
    for (int rr = 0; rr < RPB; rr++) {
        float v = acc[rr];
#pragma unroll
        for (int o = 16; o; o >>= 1) v += __shfl_xor_sync(0xffffffffu, v, o);
        if (lane == 0) s_part[warp * SP + rr] = v;
    }
    __syncthreads();
    if (tid < RPB) {
        float s = 0.f;
#pragma unroll
        for (int w = 0; w < NWARP; w++) s += s_part[w * SP + tid];
        out[blk * RPB + tid] = s;
    }
    // total gbar calls: 2 + ITER + 1 = 36 (even) -> d_flag/d_rel return to 0 for next replay
}

// ---------------- launch ----------------
extern "C" void kernel_launch(void* const* d_in, const int* in_sizes, int n_in,
                              void* d_out, int out_size) {
    const float* Xtr = (const float*)d_in[0];
    const float* ytr = (const float*)d_in[1];
    const float* Xte = (const float*)d_in[2];
    mega_kernel<<<GRID, BLOCK>>>(Xtr, ytr, Xte, (float*)d_out);
}